// round 7
// baseline (speedup 1.0000x reference)
#include <cuda_runtime.h>
#include <cstdint>

// SpectralConv1d via mma.sync (HMMA) bf16 2-way-split GEMM.
// Per k-mode: D[m][n] = sum_kk A[m][kk]*B[kk][n],  m=row, n=2o+c', kk=2i+c
//   A[m][2i+c] = x[row][i][k][c];  B[2i][2o]=wr, B[2i+1][2o]=-wi,
//   B[2i][2o+1]=wi, B[2i+1][2o+1]=wr   ->  (c0,c1) = (Re, Im) directly.
// fp32 emulated: V = Vh + Vl (bf16); D = AhBh + AhBl + AlBh (fp32 acc).
//
// CTA: 512 thr, 128 rows x 4 k-modes; warp = (mode, 32-row slice), m32n64k64.
// stage: [row][i][mode] u64 slots, row stride 133 (conflict-free frag LDS.64),
//        filled fp32 by 8B cp.async, converted in place to (hi,lo) bf16x2.
// sB: fragment-ordered [mode][split][ks][t4][n ^ 4*t4] u64 = (b0|b1), conflict-free.

#define THREADS 512
#define KT      4
#define MROWS   128
#define RSLOT   133                          // u64 slots per stage row
#define STAGE_U64 (MROWS * RSLOT)            // 17024
#define SB_OFF    (STAGE_U64 * 8)            // 136192 bytes
#define SB_U64    (KT * 2 * 4 * 4 * 64)      // 8192
#define SMEM_TOTAL (SB_OFF + SB_U64 * 8)     // 201728 bytes

__device__ __forceinline__ unsigned smem_u32(const void* p) {
    unsigned a;
    asm("{ .reg .u64 t; cvta.to.shared.u64 t, %1; cvt.u32.u64 %0, t; }" : "=r"(a) : "l"(p));
    return a;
}
__device__ __forceinline__ void cp_async8(unsigned dst, const void* src) {
    asm volatile("cp.async.ca.shared.global [%0], [%1], 8;\n" :: "r"(dst), "l"(src));
}
__device__ __forceinline__ void cp_commit() { asm volatile("cp.async.commit_group;\n"); }
__device__ __forceinline__ void cp_wait0()  { asm volatile("cp.async.wait_group 0;\n"); }

// pack two fp32 -> bf16x2 with 'lo' in the low half
__device__ __forceinline__ unsigned cvt2bf(float lo, float hi) {
    unsigned r;
    asm("cvt.rn.bf16x2.f32 %0, %1, %2;" : "=r"(r) : "f"(hi), "f"(lo));
    return r;
}
__device__ __forceinline__ unsigned long long lds64(unsigned a) {
    unsigned long long v;
    asm volatile("ld.shared.b64 %0, [%1];" : "=l"(v) : "r"(a));
    return v;
}
__device__ __forceinline__ void sts64(unsigned a, unsigned long long v) {
    asm volatile("st.shared.b64 [%0], %1;" :: "r"(a), "l"(v));
}
__device__ __forceinline__ void sts32(unsigned a, unsigned v) {
    asm volatile("st.shared.b32 [%0], %1;" :: "r"(a), "r"(v));
}
__device__ __forceinline__ void mma16816(float* c, const unsigned* a,
                                         unsigned b0, unsigned b1) {
    asm volatile(
        "mma.sync.aligned.m16n8k16.row.col.f32.bf16.bf16.f32 "
        "{%0,%1,%2,%3}, {%4,%5,%6,%7}, {%8,%9}, {%0,%1,%2,%3};"
        : "+f"(c[0]), "+f"(c[1]), "+f"(c[2]), "+f"(c[3])
        : "r"(a[0]), "r"(a[1]), "r"(a[2]), "r"(a[3]), "r"(b0), "r"(b1));
}

__global__ void __launch_bounds__(THREADS, 1)
spectral_r7_kernel(const float* __restrict__ X,
                   const float* __restrict__ W,
                   float* __restrict__ O)
{
    extern __shared__ char smem[];
    const unsigned stage = smem_u32(smem);         // u64 slots, fp32 then bf16-split
    const unsigned sB    = stage + SB_OFF;

    const int tid  = threadIdx.x;
    const int lane = tid & 31;
    const int warp = tid >> 5;
    const int gid  = lane >> 2;       // fragment group id (0..7)
    const int t4   = lane & 3;        // thread-in-group
    const int kg   = blockIdx.x * KT;
    const long rowBase = (long)blockIdx.y * MROWS;

    // ---- fill stage with raw fp32 pairs via 8B cp.async ----
    #pragma unroll
    for (int it = 0; it < 32; ++it) {
        int idx = tid + it * THREADS;              // 16384 chunks
        int m = idx & 3, i = (idx >> 2) & 31, row = idx >> 7;
        const float* src = X + (rowBase + row) * 4096 + i * 128 + (size_t)(kg + m) * 2;
        cp_async8(stage + (unsigned)(row * RSLOT + 4 * i + m) * 8, src);
    }
    cp_commit();

    // ---- build B fragments in smem (from L2-resident W) ----
    #pragma unroll
    for (int it = 0; it < 8; ++it) {
        int idx = tid + it * THREADS;              // 4096 = (o,i,md)
        int md = idx & 3, i = (idx >> 2) & 31, o = idx >> 7;
        float2 wv = *reinterpret_cast<const float2*>(
            W + (size_t)o * 4096 + i * 128 + (size_t)(kg + md) * 2);
        unsigned ph = cvt2bf(wv.x, wv.y);                       // (wr_h | wi_h)
        float wrh = __uint_as_float(ph << 16);
        float wih = __uint_as_float(ph & 0xFFFF0000u);
        unsigned pl = cvt2bf(wv.x - wrh, wv.y - wih);
        const int ks = i >> 3, half = (i >> 2) & 1, it4 = i & 3;
        const int n0 = 2 * o, n1 = 2 * o + 1;
        #pragma unroll
        for (int s = 0; s < 2; ++s) {
            unsigned p = s ? pl : ph;
            unsigned base = (unsigned)((((md * 2 + s) * 4 + ks) * 4 + it4) * 64);
            // n even: (wr, -wi) ; n odd: (wi, wr)
            sts32(sB + (base + (unsigned)(n0 ^ (it4 * 4))) * 8 + half * 4,
                  p ^ 0x80000000u);
            sts32(sB + (base + (unsigned)(n1 ^ (it4 * 4))) * 8 + half * 4,
                  (p >> 16) | (p << 16));
        }
    }

    cp_wait0();
    __syncthreads();

    // ---- convert stage in place: fp32 (xr,xi) -> (hi bf16x2 | lo bf16x2) ----
    #pragma unroll
    for (int it = 0; it < 32; ++it) {
        int idx = tid + it * THREADS;
        int m = idx & 3, i = (idx >> 2) & 31, row = idx >> 7;
        unsigned addr = stage + (unsigned)(row * RSLOT + 4 * i + m) * 8;
        unsigned long long v = lds64(addr);
        float xr, xi;
        asm("mov.b64 {%0,%1}, %2;" : "=f"(xr), "=f"(xi) : "l"(v));
        unsigned ph = cvt2bf(xr, xi);
        float xrh = __uint_as_float(ph << 16);
        float xih = __uint_as_float(ph & 0xFFFF0000u);
        unsigned pl = cvt2bf(xr - xrh, xi - xih);
        sts64(addr, ((unsigned long long)pl << 32) | ph);
    }
    __syncthreads();

    // ---- main: warp = (mode md, rows rb..rb+31); m32 n64 k64 ----
    const int md = warp & 3;
    const int rb = (warp >> 2) * 32;

    float acc[2][8][4];
    #pragma unroll
    for (int mt = 0; mt < 2; ++mt)
        #pragma unroll
        for (int nt = 0; nt < 8; ++nt)
            #pragma unroll
            for (int q = 0; q < 4; ++q) acc[mt][nt][q] = 0.0f;

    #pragma unroll 1
    for (int ks = 0; ks < 4; ++ks) {
        unsigned ah[2][4], al[2][4];
        #pragma unroll
        for (int mt = 0; mt < 2; ++mt) {
            #pragma unroll
            for (int j = 0; j < 4; ++j) {      // a0..a3
                int row = rb + mt * 16 + gid + (j & 1) * 8;
                int i   = t4 + (j >> 1) * 4 + 8 * ks;
                unsigned long long v =
                    lds64(stage + (unsigned)(row * RSLOT + 4 * i + md) * 8);
                ah[mt][j] = (unsigned)v;
                al[mt][j] = (unsigned)(v >> 32);
            }
        }
        #pragma unroll
        for (int nt = 0; nt < 8; ++nt) {
            unsigned col = (unsigned)((nt * 8 + gid) ^ (t4 * 4));
            unsigned bh_a = sB + ((unsigned)(((md * 2 + 0) * 4 + ks) * 4 + t4) * 64 + col) * 8;
            unsigned long long bh = lds64(bh_a);
            unsigned long long bl = lds64(bh_a + 4 * 4 * 64 * 8);   // split s=1 block
            unsigned bh0 = (unsigned)bh, bh1 = (unsigned)(bh >> 32);
            unsigned bl0 = (unsigned)bl, bl1 = (unsigned)(bl >> 32);
            #pragma unroll
            for (int mt = 0; mt < 2; ++mt) {
                mma16816(acc[mt][nt], ah[mt], bh0, bh1);   // hi*hi
                mma16816(acc[mt][nt], ah[mt], bl0, bl1);   // hi*lo
                mma16816(acc[mt][nt], al[mt], bh0, bh1);   // lo*hi
            }
        }
    }

    // ---- epilogue: c frags are (Re,Im) pairs -> direct float2 stores ----
    #pragma unroll
    for (int mt = 0; mt < 2; ++mt) {
        const long row = rowBase + rb + mt * 16 + gid;
        #pragma unroll
        for (int nt = 0; nt < 8; ++nt) {
            const int o = nt * 4 + t4;
            float* op = O + row * 4096 + (size_t)o * 128 + (size_t)(kg + md) * 2;
            *reinterpret_cast<float2*>(op) =
                make_float2(acc[mt][nt][0], acc[mt][nt][1]);
            *reinterpret_cast<float2*>(op + 8 * 4096) =
                make_float2(acc[mt][nt][2], acc[mt][nt][3]);
        }
    }
}

extern "C" void kernel_launch(void* const* d_in, const int* in_sizes, int n_in,
                              void* d_out, int out_size)
{
    const float* x = (const float*)d_in[0];   // (8,2048,32,64,2) fp32
    const float* w = (const float*)d_in[1];   // (32,32,64,2) fp32
    float* out = (float*)d_out;               // (8,2048,32,64,2) fp32

    cudaFuncSetAttribute(spectral_r7_kernel,
                         cudaFuncAttributeMaxDynamicSharedMemorySize, SMEM_TOTAL);
    dim3 grid(64 / KT, 16384 / MROWS);        // (16, 128) = 2048 CTAs
    spectral_r7_kernel<<<grid, THREADS, SMEM_TOTAL>>>(x, w, out);
}

// round 8
// speedup vs baseline: 1.2410x; 1.2410x over previous
#include <cuda_runtime.h>
#include <cstdint>

// SpectralConv1d via mma.sync (HMMA) bf16 2-way-split GEMM. Round 8.
// Per k-mode: D[m][n] = sum_kk A[m][kk]*B[kk][n],  n=2o+c', kk=2i+c
//   B[2i][2o]=wr, B[2i+1][2o]=-wi, B[2i][2o+1]=wi, B[2i+1][2o+1]=wr
// fp32 emulated: V=Vh+Vl (bf16); D = AhBh + AhBl + AlBh (fp32 acc).
//
// prep kernel: builds B fragments (hi/lo) for all 16 k-groups into gB (1 MB),
//   laid out in per-thread mma fragment order -> main kernel LDG.64 is
//   64B-contiguous per t4-group and L2-resident.
// main kernel: 256 thr, 32 rows x 4 modes, smem = 34 KB x-stage only,
//   3 CTAs/SM. Warp = (mode, 16-row slice): m16n64k64, 96 mma.

#define THREADS 256
#define MROWS   32
#define RSLOT   133                     // u64 slots per stage row
#define STAGE_BYTES (MROWS * RSLOT * 8) // 34048
#define KT      4

__device__ unsigned long long gB[16 * 8192];   // [kg][md][s][ks][t4][64] u64

__device__ __forceinline__ unsigned smem_u32(const void* p) {
    unsigned a;
    asm("{ .reg .u64 t; cvta.to.shared.u64 t, %1; cvt.u32.u64 %0, t; }" : "=r"(a) : "l"(p));
    return a;
}
// pack two fp32 -> bf16x2 (lo arg in low half)
__device__ __forceinline__ unsigned cvt2bf(float lo, float hi) {
    unsigned r;
    asm("cvt.rn.bf16x2.f32 %0, %1, %2;" : "=r"(r) : "f"(hi), "f"(lo));
    return r;
}
// fp32 pair -> (hi bf16x2 | lo bf16x2) u64
__device__ __forceinline__ unsigned long long split2(float xr, float xi) {
    unsigned ph = cvt2bf(xr, xi);
    float xrh = __uint_as_float(ph << 16);
    float xih = __uint_as_float(ph & 0xFFFF0000u);
    unsigned pl = cvt2bf(xr - xrh, xi - xih);
    return ((unsigned long long)pl << 32) | ph;
}
__device__ __forceinline__ unsigned long long lds64(unsigned a) {
    unsigned long long v;
    asm volatile("ld.shared.b64 %0, [%1];" : "=l"(v) : "r"(a));
    return v;
}
__device__ __forceinline__ void sts64(unsigned a, unsigned long long v) {
    asm volatile("st.shared.b64 [%0], %1;" :: "r"(a), "l"(v));
}
__device__ __forceinline__ void mma16816(float* c, const unsigned* a,
                                         unsigned b0, unsigned b1) {
    asm volatile(
        "mma.sync.aligned.m16n8k16.row.col.f32.bf16.bf16.f32 "
        "{%0,%1,%2,%3}, {%4,%5,%6,%7}, {%8,%9}, {%0,%1,%2,%3};"
        : "+f"(c[0]), "+f"(c[1]), "+f"(c[2]), "+f"(c[3])
        : "r"(a[0]), "r"(a[1]), "r"(a[2]), "r"(a[3]), "r"(b0), "r"(b1));
}

// ---- prep: build B fragments for all k-groups ----
__global__ void __launch_bounds__(THREADS)
spectral_prepB_kernel(const float* __restrict__ W)
{
    const int kgidx = blockIdx.x;            // 0..15
    const int kg    = kgidx * KT;
    unsigned* dst = reinterpret_cast<unsigned*>(gB + kgidx * 8192);

    #pragma unroll
    for (int it = 0; it < 16; ++it) {
        int idx = threadIdx.x + it * THREADS;      // 4096 = (o,i,md)
        int md = idx & 3, i = (idx >> 2) & 31, o = idx >> 7;
        float2 wv = *reinterpret_cast<const float2*>(
            W + (size_t)o * 4096 + i * 128 + (size_t)(kg + md) * 2);
        unsigned ph = cvt2bf(wv.x, wv.y);                 // (wr_h | wi_h)
        float wrh = __uint_as_float(ph << 16);
        float wih = __uint_as_float(ph & 0xFFFF0000u);
        unsigned pl = cvt2bf(wv.x - wrh, wv.y - wih);
        const int ks = i >> 3, half = (i >> 2) & 1, t4 = i & 3;
        #pragma unroll
        for (int s = 0; s < 2; ++s) {
            unsigned p = s ? pl : ph;
            unsigned base = (unsigned)((((md * 2 + s) * 4 + ks) * 4 + t4) * 64);
            // n even (2o): (wr, -wi) ; n odd (2o+1): (wi, wr)
            dst[2 * (base + 2 * o)     + half] = p ^ 0x80000000u;
            dst[2 * (base + 2 * o + 1) + half] = (p >> 16) | (p << 16);
        }
    }
}

// ---- main ----
__global__ void __launch_bounds__(THREADS, 3)
spectral_r8_kernel(const float* __restrict__ X,
                   float* __restrict__ O)
{
    extern __shared__ char smem[];
    const unsigned stage = smem_u32(smem);   // [row][i][mode] u64 (hi|lo bf16x2)

    const int tid  = threadIdx.x;
    const int lane = tid & 31;
    const int warp = tid >> 5;               // 0..7
    const int gid  = lane >> 2;              // 0..7
    const int t4   = lane & 3;
    const int kgidx = blockIdx.x;
    const int kg    = kgidx * KT;
    const long rowBase = (long)blockIdx.y * MROWS;

    // ---- X: LDG.128 (batched) -> bf16 split -> STS.64 pairs ----
    float4 pf[8];
    #pragma unroll
    for (int it = 0; it < 8; ++it) {
        int idx = tid + it * THREADS;        // 2048 = (row, i, half)
        int half = idx & 1, i = (idx >> 1) & 31, row = idx >> 6;
        pf[it] = *reinterpret_cast<const float4*>(
            X + (rowBase + row) * 4096 + i * 128 + (size_t)(kg + half * 2) * 2);
    }
    #pragma unroll
    for (int it = 0; it < 8; ++it) {
        int idx = tid + it * THREADS;
        int half = idx & 1, i = (idx >> 1) & 31, row = idx >> 6;
        unsigned a0 = stage + (unsigned)(row * RSLOT + 4 * i + 2 * half) * 8;
        sts64(a0,     split2(pf[it].x, pf[it].y));   // mode 2*half
        sts64(a0 + 8, split2(pf[it].z, pf[it].w));   // mode 2*half+1
    }
    __syncthreads();

    // ---- compute: warp = (mode md, rows rb..rb+15), m16 n64 k64 ----
    const int md = warp & 3;
    const int rb = (warp >> 2) * 16;
    const unsigned long long* Bk = gB + kgidx * 8192;

    float acc[8][4];
    #pragma unroll
    for (int nt = 0; nt < 8; ++nt)
        #pragma unroll
        for (int q = 0; q < 4; ++q) acc[nt][q] = 0.0f;

    #pragma unroll
    for (int ks = 0; ks < 4; ++ks) {
        unsigned ah[4], al[4];
        #pragma unroll
        for (int j = 0; j < 4; ++j) {
            int row = rb + gid + (j & 1) * 8;
            int i   = t4 + (j >> 1) * 4 + 8 * ks;
            unsigned long long v =
                lds64(stage + (unsigned)(row * RSLOT + 4 * i + md) * 8);
            ah[j] = (unsigned)v;
            al[j] = (unsigned)(v >> 32);
        }
        const unsigned long long* bh_p = Bk + (size_t)(((md * 2 + 0) * 4 + ks) * 4 + t4) * 64;
        const unsigned long long* bl_p = Bk + (size_t)(((md * 2 + 1) * 4 + ks) * 4 + t4) * 64;
        #pragma unroll
        for (int nt = 0; nt < 8; ++nt) {
            unsigned long long bh = bh_p[8 * nt + gid];
            unsigned long long bl = bl_p[8 * nt + gid];
            mma16816(acc[nt], ah, (unsigned)bh, (unsigned)(bh >> 32));  // hi*hi
            mma16816(acc[nt], ah, (unsigned)bl, (unsigned)(bl >> 32));  // hi*lo
            mma16816(acc[nt], al, (unsigned)bh, (unsigned)(bh >> 32));  // lo*hi
        }
    }

    // ---- epilogue: (c0,c1)=(Re,Im) row gid, (c2,c3) row gid+8 ----
    const long row0 = rowBase + rb + gid;
    #pragma unroll
    for (int nt = 0; nt < 8; ++nt) {
        const int o = nt * 4 + t4;
        float* op = O + row0 * 4096 + (size_t)o * 128 + (size_t)(kg + md) * 2;
        *reinterpret_cast<float2*>(op)            = make_float2(acc[nt][0], acc[nt][1]);
        *reinterpret_cast<float2*>(op + 8 * 4096) = make_float2(acc[nt][2], acc[nt][3]);
    }
}

extern "C" void kernel_launch(void* const* d_in, const int* in_sizes, int n_in,
                              void* d_out, int out_size)
{
    const float* x = (const float*)d_in[0];   // (8,2048,32,64,2) fp32
    const float* w = (const float*)d_in[1];   // (32,32,64,2) fp32
    float* out = (float*)d_out;               // (8,2048,32,64,2) fp32

    spectral_prepB_kernel<<<16, THREADS>>>(w);

    cudaFuncSetAttribute(spectral_r8_kernel,
                         cudaFuncAttributeMaxDynamicSharedMemorySize, STAGE_BYTES);
    dim3 grid(16, 16384 / MROWS);             // (16, 512) = 8192 CTAs
    spectral_r8_kernel<<<grid, THREADS, STAGE_BYTES>>>(x, out);
}

// round 9
// speedup vs baseline: 1.3951x; 1.1242x over previous
#include <cuda_runtime.h>
#include <cstdint>

// SpectralConv1d via mma.sync (HMMA) bf16 2-way-split GEMM. Round 9.
// Per k-mode: D[m][n] = sum_kk A[m][kk]*B[kk][n],  n=2o+c', kk=2i+c
//   B[2i][2o]=wr, B[2i+1][2o]=-wi, B[2i][2o+1]=wi, B[2i+1][2o+1]=wr
// fp32 emulated: V=Vh+Vl (bf16); D = AhBh + AhBl + AlBh (fp32 acc).
//
// R9 changes vs R8: warp tile m32n64 (B amortized over 2x rows), B fragments
// relaid out so each thread's 8 nt values are contiguous -> LDG.128, CTA = 64
// rows with 2 CTAs/SM for cross-CTA phase overlap.

#define THREADS 256
#define MROWS   64
#define RSLOT   133                     // u64 slots per stage row
#define STAGE_BYTES (MROWS * RSLOT * 8) // 68096
#define KT      4

__device__ unsigned long long gB[16 * 8192];   // [kg][md][s][ks][t4][gid][nt] u64

__device__ __forceinline__ unsigned smem_u32(const void* p) {
    unsigned a;
    asm("{ .reg .u64 t; cvta.to.shared.u64 t, %1; cvt.u32.u64 %0, t; }" : "=r"(a) : "l"(p));
    return a;
}
// pack two fp32 -> bf16x2 (lo arg in low half)
__device__ __forceinline__ unsigned cvt2bf(float lo, float hi) {
    unsigned r;
    asm("cvt.rn.bf16x2.f32 %0, %1, %2;" : "=r"(r) : "f"(hi), "f"(lo));
    return r;
}
// fp32 pair -> (hi bf16x2 | lo bf16x2) u64
__device__ __forceinline__ unsigned long long split2(float xr, float xi) {
    unsigned ph = cvt2bf(xr, xi);
    float xrh = __uint_as_float(ph << 16);
    float xih = __uint_as_float(ph & 0xFFFF0000u);
    unsigned pl = cvt2bf(xr - xrh, xi - xih);
    return ((unsigned long long)pl << 32) | ph;
}
__device__ __forceinline__ unsigned long long lds64(unsigned a) {
    unsigned long long v;
    asm volatile("ld.shared.b64 %0, [%1];" : "=l"(v) : "r"(a));
    return v;
}
__device__ __forceinline__ void sts64(unsigned a, unsigned long long v) {
    asm volatile("st.shared.b64 [%0], %1;" :: "r"(a), "l"(v));
}
__device__ __forceinline__ void mma16816(float* c, const unsigned* a,
                                         unsigned b0, unsigned b1) {
    asm volatile(
        "mma.sync.aligned.m16n8k16.row.col.f32.bf16.bf16.f32 "
        "{%0,%1,%2,%3}, {%4,%5,%6,%7}, {%8,%9}, {%0,%1,%2,%3};"
        : "+f"(c[0]), "+f"(c[1]), "+f"(c[2]), "+f"(c[3])
        : "r"(a[0]), "r"(a[1]), "r"(a[2]), "r"(a[3]), "r"(b0), "r"(b1));
}

// ---- prep: build B fragments for all k-groups (thread-contiguous nt) ----
__global__ void __launch_bounds__(THREADS)
spectral_prepB_kernel(const float* __restrict__ W)
{
    const int kgidx = blockIdx.x;            // 0..15
    const int kg    = kgidx * KT;
    unsigned* dst = reinterpret_cast<unsigned*>(gB + kgidx * 8192);

    #pragma unroll
    for (int it = 0; it < 16; ++it) {
        int idx = threadIdx.x + it * THREADS;      // 4096 = (o,i,md)
        int md = idx & 3, i = (idx >> 2) & 31, o = idx >> 7;
        float2 wv = *reinterpret_cast<const float2*>(
            W + (size_t)o * 4096 + i * 128 + (size_t)(kg + md) * 2);
        unsigned ph = cvt2bf(wv.x, wv.y);                 // (wr_h | wi_h)
        float wrh = __uint_as_float(ph << 16);
        float wih = __uint_as_float(ph & 0xFFFF0000u);
        unsigned pl = cvt2bf(wv.x - wrh, wv.y - wih);
        const int ks = i >> 3, half = (i >> 2) & 1, t4 = i & 3;
        const int n0 = 2 * o, n1 = 2 * o + 1;
        #pragma unroll
        for (int s = 0; s < 2; ++s) {
            unsigned p = s ? pl : ph;
            unsigned pre = (unsigned)(((md * 2 + s) * 4 + ks) * 4 + t4) * 8;
            // u64 idx = (pre + gid)*8 + nt ; gid = n&7, nt = n>>3
            // n even (2o): (wr, -wi) ; n odd (2o+1): (wi, wr)
            dst[2 * ((pre + (n0 & 7)) * 8 + (n0 >> 3)) + half] = p ^ 0x80000000u;
            dst[2 * ((pre + (n1 & 7)) * 8 + (n1 >> 3)) + half] = (p >> 16) | (p << 16);
        }
    }
}

// ---- main ----
__global__ void __launch_bounds__(THREADS, 2)
spectral_r9_kernel(const float* __restrict__ X,
                   float* __restrict__ O)
{
    extern __shared__ char smem[];
    const unsigned stage = smem_u32(smem);   // [row][i][mode] u64 (hi|lo bf16x2)

    const int tid  = threadIdx.x;
    const int lane = tid & 31;
    const int warp = tid >> 5;               // 0..7
    const int gid  = lane >> 2;              // 0..7
    const int t4   = lane & 3;
    const int kgidx = blockIdx.x;
    const int kg    = kgidx * KT;
    const long rowBase = (long)blockIdx.y * MROWS;

    // ---- X: LDG.128 (two batches of 8) -> bf16 split -> STS.64 pairs ----
    #pragma unroll
    for (int b = 0; b < 2; ++b) {
        float4 pf[8];
        #pragma unroll
        for (int it = 0; it < 8; ++it) {
            int idx = tid + (b * 8 + it) * THREADS;   // 4096 = (row, i, half)
            int half = idx & 1, i = (idx >> 1) & 31, row = idx >> 6;
            pf[it] = *reinterpret_cast<const float4*>(
                X + (rowBase + row) * 4096 + i * 128 + (size_t)(kg + half * 2) * 2);
        }
        #pragma unroll
        for (int it = 0; it < 8; ++it) {
            int idx = tid + (b * 8 + it) * THREADS;
            int half = idx & 1, i = (idx >> 1) & 31, row = idx >> 6;
            unsigned a0 = stage + (unsigned)(row * RSLOT + 4 * i + 2 * half) * 8;
            sts64(a0,     split2(pf[it].x, pf[it].y));   // mode 2*half
            sts64(a0 + 8, split2(pf[it].z, pf[it].w));   // mode 2*half+1
        }
    }
    __syncthreads();

    // ---- compute: warp = (mode md, rows rb..rb+31), m32 n64 k64 ----
    const int md = warp & 3;
    const int rb = (warp >> 2) * 32;
    const unsigned long long* Bk = gB + kgidx * 8192;

    float acc[2][8][4];
    #pragma unroll
    for (int mt = 0; mt < 2; ++mt)
        #pragma unroll
        for (int nt = 0; nt < 8; ++nt)
            #pragma unroll
            for (int q = 0; q < 4; ++q) acc[mt][nt][q] = 0.0f;

    #pragma unroll
    for (int ks = 0; ks < 4; ++ks) {
        // A fragments: 8 LDS.64 (hi|lo in one u64)
        unsigned ah[2][4], al[2][4];
        #pragma unroll
        for (int mt = 0; mt < 2; ++mt)
            #pragma unroll
            for (int j = 0; j < 4; ++j) {
                int row = rb + mt * 16 + gid + (j & 1) * 8;
                int i   = t4 + (j >> 1) * 4 + 8 * ks;
                unsigned long long v =
                    lds64(stage + (unsigned)(row * RSLOT + 4 * i + md) * 8);
                ah[mt][j] = (unsigned)v;
                al[mt][j] = (unsigned)(v >> 32);
            }
        // B fragments: 8 LDG.128 (nt pairs contiguous per thread)
        const ulonglong2* bh2 = reinterpret_cast<const ulonglong2*>(
            Bk + (size_t)((((md * 2 + 0) * 4 + ks) * 4 + t4) * 8 + gid) * 8);
        const ulonglong2* bl2 = reinterpret_cast<const ulonglong2*>(
            Bk + (size_t)((((md * 2 + 1) * 4 + ks) * 4 + t4) * 8 + gid) * 8);
        ulonglong2 BH[4], BL[4];
        #pragma unroll
        for (int j = 0; j < 4; ++j) { BH[j] = bh2[j]; BL[j] = bl2[j]; }

        #pragma unroll
        for (int nt = 0; nt < 8; ++nt) {
            unsigned long long bh = (nt & 1) ? BH[nt >> 1].y : BH[nt >> 1].x;
            unsigned long long bl = (nt & 1) ? BL[nt >> 1].y : BL[nt >> 1].x;
            unsigned bh0 = (unsigned)bh, bh1 = (unsigned)(bh >> 32);
            unsigned bl0 = (unsigned)bl, bl1 = (unsigned)(bl >> 32);
            #pragma unroll
            for (int mt = 0; mt < 2; ++mt) {
                mma16816(acc[mt][nt], ah[mt], bh0, bh1);  // hi*hi
                mma16816(acc[mt][nt], ah[mt], bl0, bl1);  // hi*lo
                mma16816(acc[mt][nt], al[mt], bh0, bh1);  // lo*hi
            }
        }
    }

    // ---- epilogue: (c0,c1)=(Re,Im) row gid, (c2,c3) row gid+8 ----
    #pragma unroll
    for (int mt = 0; mt < 2; ++mt) {
        const long row0 = rowBase + rb + mt * 16 + gid;
        #pragma unroll
        for (int nt = 0; nt < 8; ++nt) {
            const int o = nt * 4 + t4;
            float* op = O + row0 * 4096 + (size_t)o * 128 + (size_t)(kg + md) * 2;
            *reinterpret_cast<float2*>(op) =
                make_float2(acc[mt][nt][0], acc[mt][nt][1]);
            *reinterpret_cast<float2*>(op + 8 * 4096) =
                make_float2(acc[mt][nt][2], acc[mt][nt][3]);
        }
    }
}

extern "C" void kernel_launch(void* const* d_in, const int* in_sizes, int n_in,
                              void* d_out, int out_size)
{
    const float* x = (const float*)d_in[0];   // (8,2048,32,64,2) fp32
    const float* w = (const float*)d_in[1];   // (32,32,64,2) fp32
    float* out = (float*)d_out;               // (8,2048,32,64,2) fp32

    spectral_prepB_kernel<<<16, THREADS>>>(w);

    cudaFuncSetAttribute(spectral_r9_kernel,
                         cudaFuncAttributeMaxDynamicSharedMemorySize, STAGE_BYTES);
    dim3 grid(16, 16384 / MROWS);             // (16, 256) = 4096 CTAs
    spectral_r9_kernel<<<grid, THREADS, STAGE_BYTES>>>(x, out);
}

// round 10
// speedup vs baseline: 1.9679x; 1.4106x over previous
#include <cuda_runtime.h>
#include <cstdint>

// SpectralConv1d via mma.sync (HMMA) bf16 2-way-split GEMM. Round 10.
// Per k-mode: D[m][n] = sum_kk A[m][kk]*B[kk][n],  n=2o+c', kk=2i+c
// fp32 emulated: V=Vh+Vl (bf16); D = AhBh + AhBl + AlBh (fp32 acc).
//
// R10: minimize 128B-lines-touched per memory instruction.
//  - CTA = 32 rows x 8 modes (KT=8): X fill reads 64B/line (8 lines/LDG.128)
//  - B fragments stored lane-consecutive in gB -> 4-line LDG.128, L1-shared
//    between co-resident CTAs (grid ordered so neighbors share kg)
//  - epilogue staged in smem -> STG.128 with 64B-contiguous k-runs (8 lines)
//  - stage [row][md][i^swz] u64, row stride 260: fill STS + A LDS conflict-free

#define THREADS 256
#define MROWS   32
#define KT      8
#define RS      260                         // u64 per stage row (mod 16 = 4)
#define STAGE_BYTES (MROWS * RS * 8)        // 66560

__device__ unsigned long long gB[8 * 16384];  // [kgi][md][s][ks][j][lane][2] u64

__device__ __forceinline__ unsigned smem_u32(const void* p) {
    unsigned a;
    asm("{ .reg .u64 t; cvta.to.shared.u64 t, %1; cvt.u32.u64 %0, t; }" : "=r"(a) : "l"(p));
    return a;
}
__device__ __forceinline__ unsigned cvt2bf(float lo, float hi) {
    unsigned r;
    asm("cvt.rn.bf16x2.f32 %0, %1, %2;" : "=r"(r) : "f"(hi), "f"(lo));
    return r;
}
__device__ __forceinline__ unsigned long long split2(float xr, float xi) {
    unsigned ph = cvt2bf(xr, xi);
    float xrh = __uint_as_float(ph << 16);
    float xih = __uint_as_float(ph & 0xFFFF0000u);
    unsigned pl = cvt2bf(xr - xrh, xi - xih);
    return ((unsigned long long)pl << 32) | ph;
}
__device__ __forceinline__ unsigned long long pack2(float lo, float hi) {
    unsigned long long r;
    asm("mov.b64 %0, {%1, %2};" : "=l"(r) : "f"(lo), "f"(hi));
    return r;
}
__device__ __forceinline__ unsigned long long lds64(unsigned a) {
    unsigned long long v;
    asm volatile("ld.shared.b64 %0, [%1];" : "=l"(v) : "r"(a));
    return v;
}
__device__ __forceinline__ void sts64(unsigned a, unsigned long long v) {
    asm volatile("st.shared.b64 [%0], %1;" :: "r"(a), "l"(v));
}
__device__ __forceinline__ void mma16816(float* c, const unsigned* a,
                                         unsigned b0, unsigned b1) {
    asm volatile(
        "mma.sync.aligned.m16n8k16.row.col.f32.bf16.bf16.f32 "
        "{%0,%1,%2,%3}, {%4,%5,%6,%7}, {%8,%9}, {%0,%1,%2,%3};"
        : "+f"(c[0]), "+f"(c[1]), "+f"(c[2]), "+f"(c[3])
        : "r"(a[0]), "r"(a[1]), "r"(a[2]), "r"(a[3]), "r"(b0), "r"(b1));
}

// ---- prep: B fragments, lane-consecutive layout ----
__global__ void __launch_bounds__(THREADS)
spectral_prepB_kernel(const float* __restrict__ W)
{
    const int kgi = blockIdx.x;                 // 0..7
    const int kbase = kgi * KT;
    unsigned* dst = reinterpret_cast<unsigned*>(gB + kgi * 16384);

    #pragma unroll
    for (int it = 0; it < 32; ++it) {
        int idx = threadIdx.x + it * THREADS;   // 8192 = (o,i,md)
        int md = idx & 7, i = (idx >> 3) & 31, o = idx >> 8;
        float2 wv = *reinterpret_cast<const float2*>(
            W + (size_t)o * 4096 + i * 128 + (size_t)(kbase + md) * 2);
        unsigned ph = cvt2bf(wv.x, wv.y);       // low=wr_h, high=wi_h
        float wrh = __uint_as_float(ph << 16);
        float wih = __uint_as_float(ph & 0xFFFF0000u);
        unsigned pl = cvt2bf(wv.x - wrh, wv.y - wih);
        const int ks = i >> 3, half = (i >> 2) & 1, t4 = i & 3;
        #pragma unroll
        for (int s = 0; s < 2; ++s) {
            unsigned p = s ? pl : ph;
            #pragma unroll
            for (int c = 0; c < 2; ++c) {       // n = 2o + c
                int n = 2 * o + c;
                int gid = n & 7, nt = n >> 3, j = nt >> 1, wsel = nt & 1;
                unsigned u64i =
                    (unsigned)(((((md * 2 + s) * 4 + ks) * 4 + j) * 32
                                + (gid * 4 + t4)) * 2 + wsel);
                unsigned val = c ? ((p >> 16) | (p << 16))    // (wi, wr)
                                 : (p ^ 0x80000000u);         // (wr, -wi)
                dst[u64i * 2 + half] = val;
            }
        }
    }
}

// ---- main ----
__global__ void __launch_bounds__(THREADS, 2)
spectral_r10_kernel(const float* __restrict__ X,
                    float* __restrict__ O)
{
    extern __shared__ char smem[];
    const unsigned stage = smem_u32(smem);      // [row][md][i^swz] u64; reused as out stage

    const int tid  = threadIdx.x;
    const int lane = tid & 31;
    const int warp = tid >> 5;                  // 0..7 == md
    const int gid  = lane >> 2;
    const int t4   = lane & 3;
    const int kgi  = blockIdx.y;                // consecutive bids share kg -> B in L1
    const int kg   = kgi * KT;
    const long rowBase = (long)blockIdx.x * MROWS;

    // ---- X fill: LDG.128 (__ldcs) -> bf16 split -> 2x STS.64 ----
    #pragma unroll
    for (int it = 0; it < 16; ++it) {
        int idx = tid + it * THREADS;           // 4096 = (row, i, md2)
        int md2 = idx & 3, i = (idx >> 2) & 31, row = idx >> 7;
        float4 v = __ldcs(reinterpret_cast<const float4*>(
            X + (rowBase + row) * 4096 + i * 128 + (size_t)(kg + md2 * 2) * 2));
        int mda = 2 * md2, mdb = 2 * md2 + 1;
        int ia = i ^ ((2 * mda) & 31);
        int ib = i ^ ((2 * mdb) & 31);
        sts64(stage + (unsigned)(row * RS + mda * 32 + ia) * 8, split2(v.x, v.y));
        sts64(stage + (unsigned)(row * RS + mdb * 32 + ib) * 8, split2(v.z, v.w));
    }
    __syncthreads();

    // ---- compute: warp = mode md, rows 0..31; m32 n64 k64 ----
    const int md = warp;
    const int iswz = (2 * md) & 31;
    const unsigned long long* Bk = gB + kgi * 16384;

    float acc[2][8][4];
    #pragma unroll
    for (int mt = 0; mt < 2; ++mt)
        #pragma unroll
        for (int nt = 0; nt < 8; ++nt)
            #pragma unroll
            for (int q = 0; q < 4; ++q) acc[mt][nt][q] = 0.0f;

    #pragma unroll
    for (int ks = 0; ks < 4; ++ks) {
        // A fragments (hi|lo in one u64), conflict-free LDS.64
        unsigned ah[2][4], al[2][4];
        #pragma unroll
        for (int mt = 0; mt < 2; ++mt)
            #pragma unroll
            for (int j = 0; j < 4; ++j) {
                int row = mt * 16 + gid + (j & 1) * 8;
                int i   = (t4 + (j >> 1) * 4 + 8 * ks) ^ iswz;
                unsigned long long v =
                    lds64(stage + (unsigned)(row * RS + md * 32 + i) * 8);
                ah[mt][j] = (unsigned)v;
                al[mt][j] = (unsigned)(v >> 32);
            }
        // s=0 (hi B): lane-consecutive LDG.128 (4 lines/instr)
        {
            const ulonglong2* bp = reinterpret_cast<const ulonglong2*>(
                Bk + (size_t)((((md * 2 + 0) * 4 + ks) * 4) * 32 + lane) * 2);
            ulonglong2 BH[4];
            #pragma unroll
            for (int j = 0; j < 4; ++j) BH[j] = bp[j * 32];
            #pragma unroll
            for (int nt = 0; nt < 8; ++nt) {
                unsigned long long b = (nt & 1) ? BH[nt >> 1].y : BH[nt >> 1].x;
                unsigned b0 = (unsigned)b, b1 = (unsigned)(b >> 32);
                #pragma unroll
                for (int mt = 0; mt < 2; ++mt) {
                    mma16816(acc[mt][nt], ah[mt], b0, b1);   // hi*hi
                    mma16816(acc[mt][nt], al[mt], b0, b1);   // lo*hi
                }
            }
        }
        // s=1 (lo B)
        {
            const ulonglong2* bp = reinterpret_cast<const ulonglong2*>(
                Bk + (size_t)((((md * 2 + 1) * 4 + ks) * 4) * 32 + lane) * 2);
            ulonglong2 BL[4];
            #pragma unroll
            for (int j = 0; j < 4; ++j) BL[j] = bp[j * 32];
            #pragma unroll
            for (int nt = 0; nt < 8; ++nt) {
                unsigned long long b = (nt & 1) ? BL[nt >> 1].y : BL[nt >> 1].x;
                unsigned b0 = (unsigned)b, b1 = (unsigned)(b >> 32);
                #pragma unroll
                for (int mt = 0; mt < 2; ++mt)
                    mma16816(acc[mt][nt], ah[mt], b0, b1);   // hi*lo
            }
        }
    }
    __syncthreads();     // stage reads done -> reuse as out stage

    // ---- out stage: [row][o][md] u64 = (Re,Im) ----
    #pragma unroll
    for (int mt = 0; mt < 2; ++mt)
        #pragma unroll
        for (int nt = 0; nt < 8; ++nt) {
            int o = nt * 4 + t4;
            int r0 = mt * 16 + gid;
            sts64(stage + (unsigned)(r0 * RS + o * 8 + md) * 8,
                  pack2(acc[mt][nt][0], acc[mt][nt][1]));
            sts64(stage + (unsigned)((r0 + 8) * RS + o * 8 + md) * 8,
                  pack2(acc[mt][nt][2], acc[mt][nt][3]));
        }
    __syncthreads();

    // ---- coalesced store: per (row,o) 64B k-run via 4x16B lanes ----
    #pragma unroll
    for (int it = 0; it < 16; ++it) {
        int g = tid + it * THREADS;             // 4096 = (row, o, q)
        int q = g & 3, o = (g >> 2) & 31, row = g >> 7;
        ulonglong2 v = *reinterpret_cast<ulonglong2*>(
            smem + (size_t)(row * RS + o * 8 + q * 2) * 8);
        *reinterpret_cast<ulonglong2*>(
            O + (rowBase + row) * 4096 + (size_t)o * 128 + (size_t)(kg + q * 2) * 2)
            = v;
    }
}

extern "C" void kernel_launch(void* const* d_in, const int* in_sizes, int n_in,
                              void* d_out, int out_size)
{
    const float* x = (const float*)d_in[0];   // (8,2048,32,64,2) fp32
    const float* w = (const float*)d_in[1];   // (32,32,64,2) fp32
    float* out = (float*)d_out;               // (8,2048,32,64,2) fp32

    spectral_prepB_kernel<<<8, THREADS>>>(w);

    cudaFuncSetAttribute(spectral_r10_kernel,
                         cudaFuncAttributeMaxDynamicSharedMemorySize, STAGE_BYTES);
    dim3 grid(16384 / MROWS, 64 / KT);        // (512 rowgroups, 8 kgroups)
    spectral_r10_kernel<<<grid, THREADS, STAGE_BYTES>>>(x, out);
}